// round 1
// baseline (speedup 1.0000x reference)
#include <cuda_runtime.h>

// Izhikevich RS params baked in:
//   base = 3.0 + 0.7*5.0 = 6.5 ; i_dr = 6.5, i_mr = 6.5*0.7 = 4.55
//   I_dr = 6.5 - 0.5 + 0.5*n = 6.0 + 0.5*n
//   I_mr = 4.55 - 1.0 + 0.5*n = 3.55 + 0.5*n

__device__ double g_sum_dr;
__device__ double g_sum_mr;

__global__ void init_sums_kernel() {
    g_sum_dr = 0.0;
    g_sum_mr = 0.0;
}

__device__ __forceinline__ void izhi_step(float& v, float& u, float& r,
                                          float nz, float ibase) {
    float I = ibase + 0.5f * nz;
    v = v + (0.04f * v * v + 5.0f * v + 140.0f - u + I);
    u = u + 0.02f * (0.2f * v - u);
    bool s = (v >= 30.0f);
    float sf = s ? 1.0f : 0.0f;
    if (s) { v = -65.0f; u += 8.0f; }
    r = 0.9f * r + 0.1f * sf;
}

template <int POP>
__global__ __launch_bounds__(256)
void izhi_kernel(const float* __restrict__ noise,
                 const float* __restrict__ v0,
                 const float* __restrict__ u0,
                 const float* __restrict__ r0,
                 int n /* neurons, divisible by 4 */) {
    int tid = blockIdx.x * blockDim.x + threadIdx.x;
    int i = tid * 4;

    const float ibase = (POP == 0) ? 6.0f : 3.55f;

    float local = 0.0f;
    if (i < n) {
        float4 v = *reinterpret_cast<const float4*>(v0 + i);
        float4 u = *reinterpret_cast<const float4*>(u0 + i);
        float4 r = *reinterpret_cast<const float4*>(r0 + i);

#pragma unroll
        for (int t = 0; t < 20; t++) {
            float4 nz = *reinterpret_cast<const float4*>(
                noise + (size_t)t * (size_t)n + i);
            izhi_step(v.x, u.x, r.x, nz.x, ibase);
            izhi_step(v.y, u.y, r.y, nz.y, ibase);
            izhi_step(v.z, u.z, r.z, nz.z, ibase);
            izhi_step(v.w, u.w, r.w, nz.w, ibase);
        }
        local = (r.x + r.y) + (r.z + r.w);
    }

    // Warp reduce
#pragma unroll
    for (int off = 16; off > 0; off >>= 1)
        local += __shfl_down_sync(0xFFFFFFFFu, local, off);

    // Block reduce via shared
    __shared__ float warp_sums[8];
    int lane = threadIdx.x & 31;
    int wid = threadIdx.x >> 5;
    if (lane == 0) warp_sums[wid] = local;
    __syncthreads();
    if (wid == 0) {
        float s = (lane < 8) ? warp_sums[lane] : 0.0f;
#pragma unroll
        for (int off = 4; off > 0; off >>= 1)
            s += __shfl_down_sync(0xFFFFFFFFu, s, off);
        if (lane == 0) {
            if (POP == 0) atomicAdd(&g_sum_dr, (double)s);
            else          atomicAdd(&g_sum_mr, (double)s);
        }
    }
}

__global__ void finalize_kernel(float* out) {
    float dr_mean = (float)(g_sum_dr / 6000000.0);
    float mr_mean = (float)(g_sum_mr / 2000000.0);
    float raw = fminf(fmaxf(dr_mean * 8.0f, 0.0f), 1.0f);
    float ema = 0.9f * 0.5f + 0.1f * raw;
    float ht5 = fminf(fmaxf(ema, 0.05f), 0.95f);
    out[0] = ht5;
    out[1] = dr_mean;
    out[2] = mr_mean;
    out[3] = 1.0f - 0.3f * ht5;
    out[4] = ht5;
}

extern "C" void kernel_launch(void* const* d_in, const int* in_sizes, int n_in,
                              void* d_out, int out_size) {
    const float* noise_dr = (const float*)d_in[0];
    const float* noise_mr = (const float*)d_in[1];
    const float* v_dr = (const float*)d_in[2];
    const float* u_dr = (const float*)d_in[3];
    const float* r_dr = (const float*)d_in[4];
    const float* v_mr = (const float*)d_in[5];
    const float* u_mr = (const float*)d_in[6];
    const float* r_mr = (const float*)d_in[7];

    const int N_DR = 6000000;
    const int N_MR = 2000000;

    init_sums_kernel<<<1, 1>>>();

    int threads_dr = N_DR / 4;  // 1,500,000
    int threads_mr = N_MR / 4;  //   500,000
    int blocks_dr = (threads_dr + 255) / 256;
    int blocks_mr = (threads_mr + 255) / 256;

    izhi_kernel<0><<<blocks_dr, 256>>>(noise_dr, v_dr, u_dr, r_dr, N_DR);
    izhi_kernel<1><<<blocks_mr, 256>>>(noise_mr, v_mr, u_mr, r_mr, N_MR);

    finalize_kernel<<<1, 1>>>((float*)d_out);
}